// round 9
// baseline (speedup 1.0000x reference)
#include <cuda_runtime.h>
#include <math.h>

#define BB 16
#define TT 2048
#define DD 1024
#define CC 6
#define NPART 32    // block-level partials per batch
#define QKC 64      // d-chunks in k_qk1 (d-chunk = 16)

// ---------------- device scratch (no allocs allowed) ----------------
__device__ int   g_tok[BB * TT];
__device__ float g_q[BB * DD];
__device__ float g_qk[BB * DD];
__device__ float g_qkp[QKC * BB * DD];      // 4 MB qk partials
__device__ float g_xw[BB * DD];
__device__ float g_tmp[BB * DD];
__device__ float g_tmp2[BB * DD];
__device__ float g_pm[BB * NPART];
__device__ float g_pl[BB * NPART];
__device__ float g_pacc[BB * NPART * DD];   // 2 MB partial weighted sums

__device__ __forceinline__ float warp_sum(float v) {
#pragma unroll
    for (int o = 16; o > 0; o >>= 1) v += __shfl_down_sync(0xffffffffu, v, o);
    return v;
}
__device__ __forceinline__ float warp_allsum(float v) {
#pragma unroll
    for (int o = 16; o > 0; o >>= 1) v += __shfl_xor_sync(0xffffffffu, v, o);
    return v;
}

// ---------------- K1: detect layout (per-block, redundant) + convert; zero g_qk ----
__global__ void k_convert(const void* text, int V) {
    __shared__ int ok;
    if (threadIdx.x == 0) ok = 1;
    __syncthreads();
    const int2* t2 = (const int2*)text;
    for (int i = threadIdx.x; i < 2048; i += blockDim.x) {
        int2 v = t2[i];
        if (v.y != 0 || v.x < 0 || v.x >= V) ok = 0;
    }
    __syncthreads();
    int is64 = ok;
    int i = blockIdx.x * blockDim.x + threadIdx.x;
    if (i < BB * TT) {
        int t;
        if (is64) t = (int)((const long long*)text)[i];
        else      t = ((const int*)text)[i];
        g_tok[i] = t;
    }
    if (i < BB * DD) g_qk[i] = 0.0f;
}

// ---------------- K2a: q[b] = Wq @ xlast[b] + bq  (grid = D) ----------------
__global__ void k_q(const float* __restrict__ emb, const float* __restrict__ Wq,
                    const float* __restrict__ bq) {
    int d = blockIdx.x, t = threadIdx.x;        // 256 threads
    float4 w4 = ((const float4*)(Wq + (size_t)d * DD))[t];
    float acc[BB];
#pragma unroll
    for (int b = 0; b < BB; b++) {
        int row = g_tok[(b + 1) * TT - 1];
        float4 x = ((const float4*)(emb + (size_t)row * DD))[t];
        acc[b] = w4.x * x.x + w4.y * x.y + w4.z * x.z + w4.w * x.w;
    }
    __shared__ float red[BB][9];
    int lane = t & 31, wid = t >> 5;
#pragma unroll
    for (int b = 0; b < BB; b++) {
        float r = warp_sum(acc[b]);
        if (lane == 0) red[b][wid] = r;
    }
    __syncthreads();
    if (t < BB) {
        float s = 0.f;
#pragma unroll
        for (int w = 0; w < 8; w++) s += red[t][w];
        g_q[t * DD + d] = s + bq[d];
    }
}

// ---------------- K2b-1: qk partials, no atomics (grid (4,QKC), 256 thr) ------
__global__ void k_qk1(const float* __restrict__ Wk) {
    int t = threadIdx.x;
    int j  = blockIdx.x * 256 + t;
    int d0 = blockIdx.y * 16;
    __shared__ float shq[BB * 16];
    {
        int b = t >> 4, dd = t & 15;
        shq[t] = g_q[b * DD + d0 + dd];
    }
    __syncthreads();
    float w[16];
#pragma unroll
    for (int dd = 0; dd < 16; dd++)
        w[dd] = Wk[(size_t)(d0 + dd) * DD + j];
    float* dst = g_qkp + (size_t)blockIdx.y * BB * DD;
#pragma unroll
    for (int b = 0; b < BB; b++) {
        float a = 0.f;
#pragma unroll
        for (int dd = 0; dd < 16; dd++) a += shq[b * 16 + dd] * w[dd];
        dst[b * DD + j] = a;
    }
}

// ---------------- K2b-2: reduce partials -> g_qk (grid (64,16), 256 thr) ------
__global__ void k_qk2() {
    int i = blockIdx.x * 256 + threadIdx.x;     // i in [0, BB*DD)
    int c0 = blockIdx.y * 4;
    float s = 0.f;
#pragma unroll
    for (int c = 0; c < 4; c++) s += g_qkp[(size_t)(c0 + c) * BB * DD + i];
    atomicAdd(&g_qk[i], s);
}

// ---------------- K3: fused single-pass attention, D split in quarters ---------
// grid (NPART, BB), 256 thr = 8 warps = 2 token-groups x 4 D-quarters.
// Group grp: 32 tokens in 8 batches of 4; warp handles its 256-dim quarter.
__global__ void __launch_bounds__(256, 3) k_attn(const float* __restrict__ emb, float scale) {
    int b = blockIdx.y;
    int t = threadIdx.x, w = t >> 5, lane = t & 31;
    int grp = w >> 2, qd = w & 3;
    __shared__ float4 shqk[256];
    __shared__ float  sdots[2][2][4][4];        // [buf][grp][quarter][jj]
    __shared__ float  sm[2], sl[2];
    __shared__ float4 sacc[512];                // 8 KB: [grp][256]
    shqk[t] = ((const float4*)(g_qk + b * DD))[t];
    __syncthreads();
    float4 qv[2];
#pragma unroll
    for (int it = 0; it < 2; it++) qv[it] = shqk[qd * 64 + it * 32 + lane];

    int j0 = b * TT + blockIdx.x * 64 + grp * 32;
    float m = -1e30f, l = 0.f;
    float4 acc[2];
#pragma unroll
    for (int it = 0; it < 2; it++) acc[it] = make_float4(0.f, 0.f, 0.f, 0.f);

    for (int sub = 0; sub < 8; sub++) {
        int rows[4];
#pragma unroll
        for (int jj = 0; jj < 4; jj++) rows[jj] = g_tok[j0 + sub * 4 + jj];
        // load 4 rows (own quarter) into registers — 8 independent LDG.128
        float4 e[4][2];
#pragma unroll
        for (int jj = 0; jj < 4; jj++) {
            const float4* e4 = (const float4*)(emb + (size_t)rows[jj] * DD) + qd * 64;
#pragma unroll
            for (int it = 0; it < 2; it++) e[jj][it] = e4[it * 32 + lane];
        }
        // quarter-dots
#pragma unroll
        for (int jj = 0; jj < 4; jj++) {
            float d0 = e[jj][0].x * qv[0].x + e[jj][0].y * qv[0].y
                     + e[jj][0].z * qv[0].z + e[jj][0].w * qv[0].w;
            float d1 = e[jj][1].x * qv[1].x + e[jj][1].y * qv[1].y
                     + e[jj][1].z * qv[1].z + e[jj][1].w * qv[1].w;
            float r = warp_allsum(d0 + d1);
            if (lane == 0) sdots[sub & 1][grp][qd][jj] = r;
        }
        asm volatile("bar.sync %0, 128;" :: "r"(grp + 1) : "memory");
        // full scores (group-uniform)
        float s4[4];
#pragma unroll
        for (int jj = 0; jj < 4; jj++)
            s4[jj] = (sdots[sub & 1][grp][0][jj] + sdots[sub & 1][grp][1][jj]
                    + sdots[sub & 1][grp][2][jj] + sdots[sub & 1][grp][3][jj]) * scale;
        float mc = fmaxf(fmaxf(s4[0], s4[1]), fmaxf(s4[2], s4[3]));
        float nm = fmaxf(m, mc);
        float f  = __expf(m - nm);
        float pw[4], ls = 0.f;
#pragma unroll
        for (int jj = 0; jj < 4; jj++) { pw[jj] = __expf(s4[jj] - nm); ls += pw[jj]; }
        l = l * f + ls;
#pragma unroll
        for (int it = 0; it < 2; it++) {
            acc[it].x *= f; acc[it].y *= f; acc[it].z *= f; acc[it].w *= f;
        }
#pragma unroll
        for (int jj = 0; jj < 4; jj++) {
#pragma unroll
            for (int it = 0; it < 2; it++) {
                acc[it].x += pw[jj] * e[jj][it].x; acc[it].y += pw[jj] * e[jj][it].y;
                acc[it].z += pw[jj] * e[jj][it].z; acc[it].w += pw[jj] * e[jj][it].w;
            }
        }
        m = nm;
    }

    // ---- block combine across 2 groups (m, l are group-uniform) ----
    if (qd == 0 && lane == 0) { sm[grp] = m; sl[grp] = l; }
    __syncthreads();
    float mB = fmaxf(sm[0], sm[1]);
    float f = __expf(m - mB);                   // lane-uniform per warp
#pragma unroll
    for (int it = 0; it < 2; it++) {
        float4 a = acc[it];
        sacc[grp * 256 + qd * 64 + it * 32 + lane] =
            make_float4(a.x * f, a.y * f, a.z * f, a.w * f);
    }
    __syncthreads();
    float4 a = sacc[t];
    float4 v = sacc[256 + t];
    a.x += v.x; a.y += v.y; a.z += v.z; a.w += v.w;
    int pidx = b * NPART + blockIdx.x;
    ((float4*)(g_pacc + (size_t)pidx * DD))[t] = a;
    if (t == 0) {
        float lB = sl[0] * __expf(sm[0] - mB) + sl[1] * __expf(sm[1] - mB);
        g_pm[pidx] = mB; g_pl[pidx] = lB;
    }
}

// ---------------- K4: combine 32 partials -> g_xw  (grid = BB, 256 thr) ----------
__global__ void k_attn2() {
    int b = blockIdx.x, t = threadIdx.x;
    __shared__ float swt[NPART];
    __shared__ float sLinv;
    if (t < 32) {
        float mi = g_pm[b * NPART + t];
        float li = g_pl[b * NPART + t];
        float M = mi;
#pragma unroll
        for (int o = 16; o > 0; o >>= 1) M = fmaxf(M, __shfl_xor_sync(0xffffffffu, M, o));
        float f = __expf(mi - M);
        float L = warp_allsum(li * f);
        swt[t] = f;
        if (t == 0) sLinv = 1.0f / L;
    }
    __syncthreads();
    float4 a = make_float4(0.f, 0.f, 0.f, 0.f);
    const float4* base = (const float4*)(g_pacc + (size_t)b * NPART * DD);
#pragma unroll 8
    for (int i = 0; i < NPART; i++) {
        float w = swt[i];
        float4 v = base[(size_t)i * (DD / 4) + t];
        a.x += w * v.x; a.y += w * v.y; a.z += w * v.z; a.w += w * v.w;
    }
    float li = sLinv;
    ((float4*)(g_xw + b * DD))[t] = make_float4(a.x * li, a.y * li, a.z * li, a.w * li);
}

// ---------------- K5: tmp[b] = Wv @ xw[b] + bv + xlast[b]  (grid = D) ----------------
__global__ void k_v(const float* __restrict__ emb, const float* __restrict__ Wv,
                    const float* __restrict__ bv) {
    int d = blockIdx.x, t = threadIdx.x;
    float4 w4 = ((const float4*)(Wv + (size_t)d * DD))[t];
    float acc[BB];
#pragma unroll
    for (int b = 0; b < BB; b++) {
        float4 x = ((const float4*)(g_xw + b * DD))[t];
        acc[b] = w4.x * x.x + w4.y * x.y + w4.z * x.z + w4.w * x.w;
    }
    __shared__ float red[BB][9];
    int lane = t & 31, wid = t >> 5;
#pragma unroll
    for (int b = 0; b < BB; b++) {
        float r = warp_sum(acc[b]);
        if (lane == 0) red[b][wid] = r;
    }
    __syncthreads();
    if (t < BB) {
        float s = 0.f;
#pragma unroll
        for (int w = 0; w < 8; w++) s += red[t][w];
        int row = g_tok[(t + 1) * TT - 1];
        g_tmp[t * DD + d] = s + bv[d] + emb[(size_t)row * DD + d];
    }
}

// ---------------- K6: tmp2[b] = y + Wfc @ y + bfc, y = tmp[b]/||tmp[b]|| -------
__global__ void k_fc(const float* __restrict__ Wfc, const float* __restrict__ bfc) {
    int d = blockIdx.x, t = threadIdx.x;
    float4 w4 = ((const float4*)(Wfc + (size_t)d * DD))[t];
    float acc[BB], ssq[BB];
#pragma unroll
    for (int b = 0; b < BB; b++) {
        float4 x = ((const float4*)(g_tmp + b * DD))[t];
        acc[b] = w4.x * x.x + w4.y * x.y + w4.z * x.z + w4.w * x.w;
        ssq[b] = x.x * x.x + x.y * x.y + x.z * x.z + x.w * x.w;
    }
    __shared__ float red[BB][9];
    __shared__ float red2[BB][9];
    int lane = t & 31, wid = t >> 5;
#pragma unroll
    for (int b = 0; b < BB; b++) {
        float r = warp_sum(acc[b]);
        float r2 = warp_sum(ssq[b]);
        if (lane == 0) { red[b][wid] = r; red2[b][wid] = r2; }
    }
    __syncthreads();
    if (t < BB) {
        float s = 0.f, ss = 0.f;
#pragma unroll
        for (int w = 0; w < 8; w++) { s += red[t][w]; ss += red2[t][w]; }
        float inv = 1.0f / fmaxf(sqrtf(ss), 1e-12f);
        g_tmp2[t * DD + d] = (g_tmp[t * DD + d] + s) * inv + bfc[d];
    }
}

// ---------------- K7: l2norm + sigmoid(Wo @ z + bo) ----------------
__global__ void k_out(const float* __restrict__ Wo, const float* __restrict__ bo,
                      float* __restrict__ out) {
    int b = blockIdx.x, t = threadIdx.x;
    float4 v = ((const float4*)(g_tmp2 + b * DD))[t];
    float ss = v.x * v.x + v.y * v.y + v.z * v.z + v.w * v.w;
    __shared__ float sh[256];
    __shared__ float inv2;
    sh[t] = ss; __syncthreads();
    for (int s = 128; s > 0; s >>= 1) { if (t < s) sh[t] += sh[t + s]; __syncthreads(); }
    if (t == 0) inv2 = 1.0f / fmaxf(sqrtf(sh[0]), 1e-12f);
    __syncthreads();
    int wid = t >> 5, lane = t & 31;
    if (wid < CC) {
        float a = 0.f;
        for (int k = lane; k < DD; k += 32)
            a += Wo[wid * DD + k] * g_tmp2[b * DD + k];
        a = warp_sum(a);
        if (lane == 0) {
            float logit = a * inv2 + bo[wid];
            out[b * CC + wid] = 1.0f / (1.0f + expf(-logit));
        }
    }
}

// ---------------- launch ----------------
extern "C" void kernel_launch(void* const* d_in, const int* in_sizes, int n_in,
                              void* d_out, int out_size) {
    const void*  text = d_in[0];
    const float* emb  = (const float*)d_in[2];
    const float* Wq   = (const float*)d_in[3];
    const float* bq   = (const float*)d_in[4];
    const float* Wk   = (const float*)d_in[5];
    const float* Wv   = (const float*)d_in[7];
    const float* bv   = (const float*)d_in[8];
    const float* Wfc  = (const float*)d_in[9];
    const float* bfc  = (const float*)d_in[10];
    const float* Wo   = (const float*)d_in[11];
    const float* bo   = (const float*)d_in[12];
    int V = in_sizes[2] / DD;

    k_convert<<<(BB * TT + 255) / 256, 256>>>(text, V);
    k_q<<<DD, 256>>>(emb, Wq, bq);
    dim3 gq1(4, QKC);
    k_qk1<<<gq1, 256>>>(Wk);
    dim3 gq2(64, 16);
    k_qk2<<<gq2, 256>>>();
    dim3 gat(NPART, BB);
    k_attn<<<gat, 256>>>(emb, 1.0f / 32.0f);
    k_attn2<<<BB, 256>>>();
    k_v<<<DD, 256>>>(emb, Wv, bv);
    k_fc<<<DD, 256>>>(Wfc, bfc);
    k_out<<<BB, 256>>>(Wo, bo, (float*)d_out);
}

// round 11
// speedup vs baseline: 1.0036x; 1.0036x over previous
#include <cuda_runtime.h>
#include <math.h>
#include <stdint.h>

#define BB 16
#define TT 2048
#define DD 1024
#define CC 6
#define NPART 32    // blocks per batch in fused attention
#define QKC 32      // d-chunks in k_qk1 (d-chunk = 32)

// ---------------- device scratch (no allocs allowed) ----------------
__device__ int   g_tok[BB * TT];
__device__ float g_q[BB * DD];
__device__ float g_qk[BB * DD];
__device__ float g_qkp[QKC * BB * DD];      // 2 MB qk partials
__device__ float g_xw[BB * DD];
__device__ float g_tmp[BB * DD];
__device__ float g_tmp2[BB * DD];
__device__ float g_pm[BB * NPART];
__device__ float g_pl[BB * NPART];
__device__ float g_pacc[BB * NPART * DD];   // 2 MB partial weighted sums

__device__ __forceinline__ float warp_sum(float v) {
#pragma unroll
    for (int o = 16; o > 0; o >>= 1) v += __shfl_down_sync(0xffffffffu, v, o);
    return v;
}
__device__ __forceinline__ float warp_allsum(float v) {
#pragma unroll
    for (int o = 16; o > 0; o >>= 1) v += __shfl_xor_sync(0xffffffffu, v, o);
    return v;
}

// ---------------- K1: detect layout (per-block, redundant) + convert; zero g_qk ----
__global__ void k_convert(const void* text, int V) {
    __shared__ int ok;
    if (threadIdx.x == 0) ok = 1;
    __syncthreads();
    const int2* t2 = (const int2*)text;
    for (int i = threadIdx.x; i < 2048; i += blockDim.x) {
        int2 v = t2[i];
        if (v.y != 0 || v.x < 0 || v.x >= V) ok = 0;
    }
    __syncthreads();
    int is64 = ok;
    int i = blockIdx.x * blockDim.x + threadIdx.x;
    if (i < BB * TT) {
        int t;
        if (is64) t = (int)((const long long*)text)[i];
        else      t = ((const int*)text)[i];
        g_tok[i] = t;
    }
    if (i < BB * DD) g_qk[i] = 0.0f;
}

// ---------------- K2a: q[b] = Wq @ xlast[b] + bq  (grid = D) ----------------
__global__ void k_q(const float* __restrict__ emb, const float* __restrict__ Wq,
                    const float* __restrict__ bq) {
    int d = blockIdx.x, t = threadIdx.x;        // 256 threads
    float4 w4 = ((const float4*)(Wq + (size_t)d * DD))[t];
    float acc[BB];
#pragma unroll
    for (int b = 0; b < BB; b++) {
        int row = g_tok[(b + 1) * TT - 1];
        float4 x = ((const float4*)(emb + (size_t)row * DD))[t];
        acc[b] = w4.x * x.x + w4.y * x.y + w4.z * x.z + w4.w * x.w;
    }
    __shared__ float red[BB][9];
    int lane = t & 31, wid = t >> 5;
#pragma unroll
    for (int b = 0; b < BB; b++) {
        float r = warp_sum(acc[b]);
        if (lane == 0) red[b][wid] = r;
    }
    __syncthreads();
    if (t < BB) {
        float s = 0.f;
#pragma unroll
        for (int w = 0; w < 8; w++) s += red[t][w];
        g_q[t * DD + d] = s + bq[d];
    }
}

// ---------------- K2b-1: qk partials, no atomics (grid (4,QKC), 256 thr) ------
__global__ void k_qk1(const float* __restrict__ Wk) {
    int t = threadIdx.x;
    int j  = blockIdx.x * 256 + t;
    int d0 = blockIdx.y * 32;
    __shared__ float shq[BB * 32];
#pragma unroll
    for (int i = t; i < BB * 32; i += 256) {
        int b = i >> 5, dd = i & 31;
        shq[i] = g_q[b * DD + d0 + dd];
    }
    __syncthreads();
    float w[32];
#pragma unroll
    for (int dd = 0; dd < 32; dd++)
        w[dd] = Wk[(size_t)(d0 + dd) * DD + j];
    float* dst = g_qkp + (size_t)blockIdx.y * BB * DD;
#pragma unroll
    for (int b = 0; b < BB; b++) {
        float a = 0.f;
#pragma unroll
        for (int dd = 0; dd < 32; dd++) a += shq[b * 32 + dd] * w[dd];
        dst[b * DD + j] = a;
    }
}

// ---------------- K2b-2: reduce partials -> g_qk (grid (64,8), 256 thr) -------
__global__ void k_qk2() {
    int i = blockIdx.x * 256 + threadIdx.x;     // i in [0, BB*DD)
    int c0 = blockIdx.y * 4;
    float s = 0.f;
#pragma unroll
    for (int c = 0; c < 4; c++) s += g_qkp[(size_t)(c0 + c) * BB * DD + i];
    atomicAdd(&g_qk[i], s);
}

// ---------------- K3: fused single-pass attention via cp.async smem pipeline ---
// grid (NPART, BB), 256 thr = 8 warps. Block: 64 tokens, 8 stages x 8 rows.
// All threads cooperatively cp.async the next stage's rows (32 KB) while each
// warp consumes one full row of the current stage from smem.
// Dynamic smem: [0,4KB) qk tile | [4KB, 4KB+64KB) double-buffered rows.
__global__ void __launch_bounds__(256, 2) k_attn(const float* __restrict__ emb, float scale) {
    extern __shared__ char sdyn[];
    __shared__ float sm[8], sl[8];
    int b = blockIdx.y;
    int t = threadIdx.x, w = t >> 5, lane = t & 31;

    unsigned int sbase;
    asm("{ .reg .u64 tt; cvta.to.shared.u64 tt, %1; cvt.u32.u64 %0, tt; }"
        : "=r"(sbase) : "l"(sdyn));
    unsigned int rows_base = sbase + 4096;

    int j0 = b * TT + blockIdx.x * 64;

    // ---- issue stage 0 loads first (overlap with qk tile load) ----
    {
        int jbase = j0;
#pragma unroll
        for (int r = 0; r < 8; r++) {
            int row = g_tok[jbase + r];
            const float* src = emb + (size_t)row * DD;
            unsigned int dst = rows_base + r * 4096 + t * 16;
            asm volatile("cp.async.cg.shared.global [%0], [%1], 16;"
                         :: "r"(dst), "l"(src + t * 4) : "memory");
        }
        asm volatile("cp.async.commit_group;" ::: "memory");
    }

    // ---- qk tile -> smem -> registers ----
    float4* qk4 = (float4*)sdyn;
    qk4[t] = ((const float4*)(g_qk + b * DD))[t];
    __syncthreads();
    float4 qv[8];
#pragma unroll
    for (int it = 0; it < 8; it++) qv[it] = qk4[it * 32 + lane];

    float m = -1e30f, l = 0.f;
    float4 acc[8];
#pragma unroll
    for (int it = 0; it < 8; it++) acc[it] = make_float4(0.f, 0.f, 0.f, 0.f);

    for (int s = 0; s < 8; s++) {
        if (s < 7) {   // issue stage s+1 into the other buffer
            int jbase = j0 + (s + 1) * 8;
            unsigned int buf = rows_base + ((s + 1) & 1) * 32768;
#pragma unroll
            for (int r = 0; r < 8; r++) {
                int row = g_tok[jbase + r];
                const float* src = emb + (size_t)row * DD;
                unsigned int dst = buf + r * 4096 + t * 16;
                asm volatile("cp.async.cg.shared.global [%0], [%1], 16;"
                             :: "r"(dst), "l"(src + t * 4) : "memory");
            }
            asm volatile("cp.async.commit_group;" ::: "memory");
            asm volatile("cp.async.wait_group 1;" ::: "memory");
        } else {
            asm volatile("cp.async.wait_group 0;" ::: "memory");
        }
        __syncthreads();

        // ---- consume: warp w takes row w of stage s ----
        const float4* rp = (const float4*)(sdyn + 4096 + (s & 1) * 32768 + w * 4096);
        float dp = 0.f;
#pragma unroll
        for (int it = 0; it < 8; it++) {
            float4 e = rp[it * 32 + lane];
            dp += e.x * qv[it].x + e.y * qv[it].y + e.z * qv[it].z + e.w * qv[it].w;
        }
        float sc = warp_allsum(dp) * scale;
        float nm = fmaxf(m, sc);
        float f  = __expf(m - nm);
        float pw = __expf(sc - nm);
        l = l * f + pw;
#pragma unroll
        for (int it = 0; it < 8; it++) {
            float4 e = rp[it * 32 + lane];
            acc[it].x = acc[it].x * f + pw * e.x;
            acc[it].y = acc[it].y * f + pw * e.y;
            acc[it].z = acc[it].z * f + pw * e.z;
            acc[it].w = acc[it].w * f + pw * e.w;
        }
        m = nm;
        __syncthreads();   // protect buffer (s&1) before it is reloaded at s+2
    }

    // ---- block combine across 8 warps (reuse rows region as staging) ----
    if (lane == 0) { sm[w] = m; sl[w] = l; }
    __syncthreads();
    float mB = sm[0];
#pragma unroll
    for (int ww = 1; ww < 8; ww++) mB = fmaxf(mB, sm[ww]);
    float f = __expf(m - mB);                   // lane-uniform per warp
    float4* sacc = (float4*)(sdyn + 4096);
#pragma unroll
    for (int it = 0; it < 8; it++) {
        float4 a = acc[it];
        sacc[w * 256 + it * 32 + lane] =
            make_float4(a.x * f, a.y * f, a.z * f, a.w * f);
    }
    __syncthreads();
    float4 a = sacc[t];
#pragma unroll
    for (int ww = 1; ww < 8; ww++) {
        float4 v = sacc[ww * 256 + t];
        a.x += v.x; a.y += v.y; a.z += v.z; a.w += v.w;
    }
    int pidx = b * NPART + blockIdx.x;
    ((float4*)(g_pacc + (size_t)pidx * DD))[t] = a;
    if (t == 0) {
        float lB = 0.f;
#pragma unroll
        for (int ww = 0; ww < 8; ww++) lB += sl[ww] * __expf(sm[ww] - mB);
        g_pm[pidx] = mB; g_pl[pidx] = lB;
    }
}

// ---------------- K4: combine 32 partials -> g_xw  (grid = BB, 256 thr) ----------
__global__ void k_attn2() {
    int b = blockIdx.x, t = threadIdx.x;
    __shared__ float swt[NPART];
    __shared__ float sLinv;
    if (t < 32) {
        float mi = g_pm[b * NPART + t];
        float li = g_pl[b * NPART + t];
        float M = mi;
#pragma unroll
        for (int o = 16; o > 0; o >>= 1) M = fmaxf(M, __shfl_xor_sync(0xffffffffu, M, o));
        float f = __expf(mi - M);
        float L = warp_allsum(li * f);
        swt[t] = f;
        if (t == 0) sLinv = 1.0f / L;
    }
    __syncthreads();
    float4 a = make_float4(0.f, 0.f, 0.f, 0.f);
    const float4* base = (const float4*)(g_pacc + (size_t)b * NPART * DD);
#pragma unroll 8
    for (int i = 0; i < NPART; i++) {
        float w = swt[i];
        float4 v = base[(size_t)i * (DD / 4) + t];
        a.x += w * v.x; a.y += w * v.y; a.z += w * v.z; a.w += w * v.w;
    }
    float li = sLinv;
    ((float4*)(g_xw + b * DD))[t] = make_float4(a.x * li, a.y * li, a.z * li, a.w * li);
}

// ---------------- K5: tmp[b] = Wv @ xw[b] + bv + xlast[b]  (grid = D) ----------------
__global__ void k_v(const float* __restrict__ emb, const float* __restrict__ Wv,
                    const float* __restrict__ bv) {
    int d = blockIdx.x, t = threadIdx.x;
    float4 w4 = ((const float4*)(Wv + (size_t)d * DD))[t];
    float acc[BB];
#pragma unroll
    for (int b = 0; b < BB; b++) {
        float4 x = ((const float4*)(g_xw + b * DD))[t];
        acc[b] = w4.x * x.x + w4.y * x.y + w4.z * x.z + w4.w * x.w;
    }
    __shared__ float red[BB][9];
    int lane = t & 31, wid = t >> 5;
#pragma unroll
    for (int b = 0; b < BB; b++) {
        float r = warp_sum(acc[b]);
        if (lane == 0) red[b][wid] = r;
    }
    __syncthreads();
    if (t < BB) {
        float s = 0.f;
#pragma unroll
        for (int w = 0; w < 8; w++) s += red[t][w];
        int row = g_tok[(t + 1) * TT - 1];
        g_tmp[t * DD + d] = s + bv[d] + emb[(size_t)row * DD + d];
    }
}

// ---------------- K6: tmp2[b] = y + Wfc @ y + bfc, y = tmp[b]/||tmp[b]|| -------
__global__ void k_fc(const float* __restrict__ Wfc, const float* __restrict__ bfc) {
    int d = blockIdx.x, t = threadIdx.x;
    float4 w4 = ((const float4*)(Wfc + (size_t)d * DD))[t];
    float acc[BB], ssq[BB];
#pragma unroll
    for (int b = 0; b < BB; b++) {
        float4 x = ((const float4*)(g_tmp + b * DD))[t];
        acc[b] = w4.x * x.x + w4.y * x.y + w4.z * x.z + w4.w * x.w;
        ssq[b] = x.x * x.x + x.y * x.y + x.z * x.z + x.w * x.w;
    }
    __shared__ float red[BB][9];
    __shared__ float red2[BB][9];
    int lane = t & 31, wid = t >> 5;
#pragma unroll
    for (int b = 0; b < BB; b++) {
        float r = warp_sum(acc[b]);
        float r2 = warp_sum(ssq[b]);
        if (lane == 0) { red[b][wid] = r; red2[b][wid] = r2; }
    }
    __syncthreads();
    if (t < BB) {
        float s = 0.f, ss = 0.f;
#pragma unroll
        for (int w = 0; w < 8; w++) { s += red[t][w]; ss += red2[t][w]; }
        float inv = 1.0f / fmaxf(sqrtf(ss), 1e-12f);
        g_tmp2[t * DD + d] = (g_tmp[t * DD + d] + s) * inv + bfc[d];
    }
}

// ---------------- K7: l2norm + sigmoid(Wo @ z + bo) ----------------
__global__ void k_out(const float* __restrict__ Wo, const float* __restrict__ bo,
                      float* __restrict__ out) {
    int b = blockIdx.x, t = threadIdx.x;
    float4 v = ((const float4*)(g_tmp2 + b * DD))[t];
    float ss = v.x * v.x + v.y * v.y + v.z * v.z + v.w * v.w;
    __shared__ float sh[256];
    __shared__ float inv2;
    sh[t] = ss; __syncthreads();
    for (int s = 128; s > 0; s >>= 1) { if (t < s) sh[t] += sh[t + s]; __syncthreads(); }
    if (t == 0) inv2 = 1.0f / fmaxf(sqrtf(sh[0]), 1e-12f);
    __syncthreads();
    int wid = t >> 5, lane = t & 31;
    if (wid < CC) {
        float a = 0.f;
        for (int k = lane; k < DD; k += 32)
            a += Wo[wid * DD + k] * g_tmp2[b * DD + k];
        a = warp_sum(a);
        if (lane == 0) {
            float logit = a * inv2 + bo[wid];
            out[b * CC + wid] = 1.0f / (1.0f + expf(-logit));
        }
    }
}

// ---------------- launch ----------------
extern "C" void kernel_launch(void* const* d_in, const int* in_sizes, int n_in,
                              void* d_out, int out_size) {
    const void*  text = d_in[0];
    const float* emb  = (const float*)d_in[2];
    const float* Wq   = (const float*)d_in[3];
    const float* bq   = (const float*)d_in[4];
    const float* Wk   = (const float*)d_in[5];
    const float* Wv   = (const float*)d_in[7];
    const float* bv   = (const float*)d_in[8];
    const float* Wfc  = (const float*)d_in[9];
    const float* bfc  = (const float*)d_in[10];
    const float* Wo   = (const float*)d_in[11];
    const float* bo   = (const float*)d_in[12];
    int V = in_sizes[2] / DD;

    const int ATTN_SMEM = 4096 + 2 * 8 * 4096;   // 69632 bytes
    cudaFuncSetAttribute(k_attn, cudaFuncAttributeMaxDynamicSharedMemorySize, ATTN_SMEM);

    k_convert<<<(BB * TT + 255) / 256, 256>>>(text, V);
    k_q<<<DD, 256>>>(emb, Wq, bq);
    dim3 gq1(4, QKC);
    k_qk1<<<gq1, 256>>>(Wk);
    dim3 gq2(64, 8);
    k_qk2<<<gq2, 256>>>();
    dim3 gat(NPART, BB);
    k_attn<<<gat, 256, ATTN_SMEM>>>(emb, 1.0f / 32.0f);
    k_attn2<<<BB, 256>>>();
    k_v<<<DD, 256>>>(emb, Wv, bv);
    k_fc<<<DD, 256>>>(Wfc, bfc);
    k_out<<<BB, 256>>>(Wo, bo, (float*)d_out);
}

// round 12
// speedup vs baseline: 1.0732x; 1.0693x over previous
#include <cuda_runtime.h>
#include <math.h>
#include <stdint.h>

#define BB 16
#define TT 2048
#define DD 1024
#define CC 6
#define NPART 32    // block-level partials per batch
#define QKC 32      // d-chunks in k_qk1 (d-chunk = 32)

// ---------------- device scratch (no allocs allowed) ----------------
__device__ int   g_tok[BB * TT];
__device__ float g_q[BB * DD];
__device__ float g_qk[BB * DD];
__device__ float g_qkp[QKC * BB * DD];      // 2 MB qk partials
__device__ float g_xw[BB * DD];
__device__ float g_tmp[BB * DD];
__device__ float g_tmp2[BB * DD];
__device__ float g_pm[BB * NPART];
__device__ float g_pl[BB * NPART];
__device__ float g_pacc[BB * NPART * DD];   // 2 MB partial weighted sums

__device__ __forceinline__ float warp_sum(float v) {
#pragma unroll
    for (int o = 16; o > 0; o >>= 1) v += __shfl_down_sync(0xffffffffu, v, o);
    return v;
}
__device__ __forceinline__ float warp_allsum(float v) {
#pragma unroll
    for (int o = 16; o > 0; o >>= 1) v += __shfl_xor_sync(0xffffffffu, v, o);
    return v;
}

// ---------------- K1: q[b] = Wq @ xlast[b] + bq  (grid = D) ------------------
// Also: per-block layout detect (64 int2 probe) + converts 32 tokens per block
// into g_tok (1024 blocks x 32 = 32768). Last tokens read directly from text.
__global__ void k_q(const void* __restrict__ text, const float* __restrict__ emb,
                    const float* __restrict__ Wq, const float* __restrict__ bq, int V) {
    int d = blockIdx.x, t = threadIdx.x;        // 256 threads
    __shared__ int s_ok;
    if (t == 0) s_ok = 1;
    __syncthreads();
    {   // probe first 64 int64-slots (512 B): int64 layout iff all high words 0
        int2 v = ((const int2*)text)[t & 63];
        if (v.y != 0 || v.x < 0 || v.x >= V) s_ok = 0;
    }
    __syncthreads();
    int is64 = s_ok;
    // convert this block's 32 tokens
    if (t < 32) {
        int idx = d * 32 + t;
        g_tok[idx] = is64 ? (int)((const long long*)text)[idx]
                          : ((const int*)text)[idx];
    }
    // GEMV row d
    float4 w4 = ((const float4*)(Wq + (size_t)d * DD))[t];
    float acc[BB];
#pragma unroll
    for (int b = 0; b < BB; b++) {
        int li = (b + 1) * TT - 1;
        int row = is64 ? (int)((const long long*)text)[li] : ((const int*)text)[li];
        float4 x = ((const float4*)(emb + (size_t)row * DD))[t];
        acc[b] = w4.x * x.x + w4.y * x.y + w4.z * x.z + w4.w * x.w;
    }
    __shared__ float red[BB][9];
    int lane = t & 31, wid = t >> 5;
#pragma unroll
    for (int b = 0; b < BB; b++) {
        float r = warp_sum(acc[b]);
        if (lane == 0) red[b][wid] = r;
    }
    __syncthreads();
    if (t < BB) {
        float s = 0.f;
#pragma unroll
        for (int w = 0; w < 8; w++) s += red[t][w];
        g_q[t * DD + d] = s + bq[d];
    }
}

// ---------------- K2: qk partials, no atomics (grid (4,QKC), 256 thr) --------
__global__ void k_qk1(const float* __restrict__ Wk) {
    int t = threadIdx.x;
    int j  = blockIdx.x * 256 + t;
    int d0 = blockIdx.y * 32;
    __shared__ float shq[BB * 32];
#pragma unroll
    for (int i = t; i < BB * 32; i += 256) {
        int b = i >> 5, dd = i & 31;
        shq[i] = g_q[b * DD + d0 + dd];
    }
    __syncthreads();
    float w[32];
#pragma unroll
    for (int dd = 0; dd < 32; dd++)
        w[dd] = Wk[(size_t)(d0 + dd) * DD + j];
    float* dst = g_qkp + (size_t)blockIdx.y * BB * DD;
#pragma unroll
    for (int b = 0; b < BB; b++) {
        float a = 0.f;
#pragma unroll
        for (int dd = 0; dd < 32; dd++) a += shq[b * 32 + dd] * w[dd];
        dst[b * DD + j] = a;
    }
}

// ---------------- K3: full reduce partials -> g_qk (grid 64, 256 thr) --------
// 32 independent coalesced loads per thread; no atomics, no pre-zeroing.
__global__ void k_qk2() {
    int i = blockIdx.x * 256 + threadIdx.x;     // i in [0, BB*DD)
    float s = 0.f;
#pragma unroll
    for (int c = 0; c < QKC; c++) s += g_qkp[(size_t)c * BB * DD + i];
    g_qk[i] = s;
}

// ---------------- K4: fused single-pass attention, D split across warp pairs ---
// grid (NPART, BB), 256 thr = 8 warps = 4 pairs x 2 D-halves.
// Pair pp: 16 tokens in 4 batches of 4; rows stay in registers across
// dot -> pair-exchange (named barrier) -> softmax -> weighted accumulate.
__global__ void __launch_bounds__(256, 2) k_attn(const float* __restrict__ emb, float scale) {
    int b = blockIdx.y;
    int t = threadIdx.x, w = t >> 5, lane = t & 31;
    int pp = w >> 1, h = w & 1;
    __shared__ float4 shqk[256];
    __shared__ float  sdots[2][4][2][4];        // [buf][pair][half][jj]
    __shared__ float  sm[4], sl[4];
    __shared__ float4 sacc[1024];               // 16 KB
    shqk[t] = ((const float4*)(g_qk + b * DD))[t];
    __syncthreads();
    float4 qv[4];
#pragma unroll
    for (int it = 0; it < 4; it++) qv[it] = shqk[h * 128 + it * 32 + lane];

    int j0 = b * TT + blockIdx.x * 64 + pp * 16;
    float m = -1e30f, l = 0.f;
    float4 acc[4];
#pragma unroll
    for (int it = 0; it < 4; it++) acc[it] = make_float4(0.f, 0.f, 0.f, 0.f);

#pragma unroll
    for (int sub = 0; sub < 4; sub++) {
        int rows[4];
#pragma unroll
        for (int jj = 0; jj < 4; jj++) rows[jj] = g_tok[j0 + sub * 4 + jj];
        // load 4 rows (own half) into registers — 16 independent LDG.128
        float4 e[4][4];
#pragma unroll
        for (int jj = 0; jj < 4; jj++) {
            const float4* e4 = (const float4*)(emb + (size_t)rows[jj] * DD) + h * 128;
#pragma unroll
            for (int it = 0; it < 4; it++) e[jj][it] = e4[it * 32 + lane];
        }
        // half-dots
        float dd4[4];
#pragma unroll
        for (int jj = 0; jj < 4; jj++) {
            float d = 0.f;
#pragma unroll
            for (int it = 0; it < 4; it++)
                d += e[jj][it].x * qv[it].x + e[jj][it].y * qv[it].y
                   + e[jj][it].z * qv[it].z + e[jj][it].w * qv[it].w;
            dd4[jj] = d;
        }
#pragma unroll
        for (int jj = 0; jj < 4; jj++) {
            float r = warp_allsum(dd4[jj]);
            if (lane == 0) sdots[sub & 1][pp][h][jj] = r;
        }
        asm volatile("bar.sync %0, 64;" :: "r"(pp + 1) : "memory");
        // full scores (pair-uniform)
        float s4[4];
#pragma unroll
        for (int jj = 0; jj < 4; jj++)
            s4[jj] = (sdots[sub & 1][pp][0][jj] + sdots[sub & 1][pp][1][jj]) * scale;
        float mc = fmaxf(fmaxf(s4[0], s4[1]), fmaxf(s4[2], s4[3]));
        float nm = fmaxf(m, mc);
        float f  = __expf(m - nm);
        float pw[4], ls = 0.f;
#pragma unroll
        for (int jj = 0; jj < 4; jj++) { pw[jj] = __expf(s4[jj] - nm); ls += pw[jj]; }
        l = l * f + ls;
#pragma unroll
        for (int it = 0; it < 4; it++) {
            acc[it].x *= f; acc[it].y *= f; acc[it].z *= f; acc[it].w *= f;
        }
#pragma unroll
        for (int jj = 0; jj < 4; jj++) {
#pragma unroll
            for (int it = 0; it < 4; it++) {
                acc[it].x += pw[jj] * e[jj][it].x; acc[it].y += pw[jj] * e[jj][it].y;
                acc[it].z += pw[jj] * e[jj][it].z; acc[it].w += pw[jj] * e[jj][it].w;
            }
        }
        m = nm;
    }

    // ---- block combine across 4 pairs (m, l are pair-uniform) ----
    if (h == 0 && lane == 0) { sm[pp] = m; sl[pp] = l; }
    __syncthreads();
    float mB = fmaxf(fmaxf(sm[0], sm[1]), fmaxf(sm[2], sm[3]));
    float f = __expf(m - mB);                   // lane-uniform per warp
#pragma unroll
    for (int it = 0; it < 4; it++) {
        float4 a = acc[it];
        sacc[pp * 256 + h * 128 + it * 32 + lane] =
            make_float4(a.x * f, a.y * f, a.z * f, a.w * f);
    }
    __syncthreads();
    float4 a = sacc[t];
#pragma unroll
    for (int gg = 1; gg < 4; gg++) {
        float4 v = sacc[gg * 256 + t];
        a.x += v.x; a.y += v.y; a.z += v.z; a.w += v.w;
    }
    int pidx = b * NPART + blockIdx.x;
    ((float4*)(g_pacc + (size_t)pidx * DD))[t] = a;
    if (t == 0) {
        float lB = 0.f;
#pragma unroll
        for (int gg = 0; gg < 4; gg++) lB += sl[gg] * __expf(sm[gg] - mB);
        g_pm[pidx] = mB; g_pl[pidx] = lB;
    }
}

// ---------------- K5: combine 32 partials -> g_xw  (grid = BB, 256 thr) ----------
__global__ void k_attn2() {
    int b = blockIdx.x, t = threadIdx.x;
    __shared__ float swt[NPART];
    __shared__ float sLinv;
    if (t < 32) {
        float mi = g_pm[b * NPART + t];
        float li = g_pl[b * NPART + t];
        float M = mi;
#pragma unroll
        for (int o = 16; o > 0; o >>= 1) M = fmaxf(M, __shfl_xor_sync(0xffffffffu, M, o));
        float f = __expf(mi - M);
        float L = warp_allsum(li * f);
        swt[t] = f;
        if (t == 0) sLinv = 1.0f / L;
    }
    __syncthreads();
    float4 a = make_float4(0.f, 0.f, 0.f, 0.f);
    const float4* base = (const float4*)(g_pacc + (size_t)b * NPART * DD);
#pragma unroll 8
    for (int i = 0; i < NPART; i++) {
        float w = swt[i];
        float4 v = base[(size_t)i * (DD / 4) + t];
        a.x += w * v.x; a.y += w * v.y; a.z += w * v.z; a.w += w * v.w;
    }
    float li = sLinv;
    ((float4*)(g_xw + b * DD))[t] = make_float4(a.x * li, a.y * li, a.z * li, a.w * li);
}

// ---------------- K6: tmp[b] = Wv @ xw[b] + bv + xlast[b]  (grid = D) ----------------
__global__ void k_v(const float* __restrict__ emb, const float* __restrict__ Wv,
                    const float* __restrict__ bv) {
    int d = blockIdx.x, t = threadIdx.x;
    float4 w4 = ((const float4*)(Wv + (size_t)d * DD))[t];
    float acc[BB];
#pragma unroll
    for (int b = 0; b < BB; b++) {
        float4 x = ((const float4*)(g_xw + b * DD))[t];
        acc[b] = w4.x * x.x + w4.y * x.y + w4.z * x.z + w4.w * x.w;
    }
    __shared__ float red[BB][9];
    int lane = t & 31, wid = t >> 5;
#pragma unroll
    for (int b = 0; b < BB; b++) {
        float r = warp_sum(acc[b]);
        if (lane == 0) red[b][wid] = r;
    }
    __syncthreads();
    if (t < BB) {
        float s = 0.f;
#pragma unroll
        for (int w = 0; w < 8; w++) s += red[t][w];
        int row = g_tok[(t + 1) * TT - 1];
        g_tmp[t * DD + d] = s + bv[d] + emb[(size_t)row * DD + d];
    }
}

// ---------------- K7: tmp2[b] = y + Wfc @ y + bfc, y = tmp[b]/||tmp[b]|| -------
__global__ void k_fc(const float* __restrict__ Wfc, const float* __restrict__ bfc) {
    int d = blockIdx.x, t = threadIdx.x;
    float4 w4 = ((const float4*)(Wfc + (size_t)d * DD))[t];
    float acc[BB], ssq[BB];
#pragma unroll
    for (int b = 0; b < BB; b++) {
        float4 x = ((const float4*)(g_tmp + b * DD))[t];
        acc[b] = w4.x * x.x + w4.y * x.y + w4.z * x.z + w4.w * x.w;
        ssq[b] = x.x * x.x + x.y * x.y + x.z * x.z + x.w * x.w;
    }
    __shared__ float red[BB][9];
    __shared__ float red2[BB][9];
    int lane = t & 31, wid = t >> 5;
#pragma unroll
    for (int b = 0; b < BB; b++) {
        float r = warp_sum(acc[b]);
        float r2 = warp_sum(ssq[b]);
        if (lane == 0) { red[b][wid] = r; red2[b][wid] = r2; }
    }
    __syncthreads();
    if (t < BB) {
        float s = 0.f, ss = 0.f;
#pragma unroll
        for (int w = 0; w < 8; w++) { s += red[t][w]; ss += red2[t][w]; }
        float inv = 1.0f / fmaxf(sqrtf(ss), 1e-12f);
        g_tmp2[t * DD + d] = (g_tmp[t * DD + d] + s) * inv + bfc[d];
    }
}

// ---------------- K8: l2norm + sigmoid(Wo @ z + bo) ----------------
__global__ void k_out(const float* __restrict__ Wo, const float* __restrict__ bo,
                      float* __restrict__ out) {
    int b = blockIdx.x, t = threadIdx.x;
    float4 v = ((const float4*)(g_tmp2 + b * DD))[t];
    float ss = v.x * v.x + v.y * v.y + v.z * v.z + v.w * v.w;
    __shared__ float sh[256];
    __shared__ float inv2;
    sh[t] = ss; __syncthreads();
    for (int s = 128; s > 0; s >>= 1) { if (t < s) sh[t] += sh[t + s]; __syncthreads(); }
    if (t == 0) inv2 = 1.0f / fmaxf(sqrtf(sh[0]), 1e-12f);
    __syncthreads();
    int wid = t >> 5, lane = t & 31;
    if (wid < CC) {
        float a = 0.f;
        for (int k = lane; k < DD; k += 32)
            a += Wo[wid * DD + k] * g_tmp2[b * DD + k];
        a = warp_sum(a);
        if (lane == 0) {
            float logit = a * inv2 + bo[wid];
            out[b * CC + wid] = 1.0f / (1.0f + expf(-logit));
        }
    }
}

// ---------------- launch ----------------
extern "C" void kernel_launch(void* const* d_in, const int* in_sizes, int n_in,
                              void* d_out, int out_size) {
    const void*  text = d_in[0];
    const float* emb  = (const float*)d_in[2];
    const float* Wq   = (const float*)d_in[3];
    const float* bq   = (const float*)d_in[4];
    const float* Wk   = (const float*)d_in[5];
    const float* Wv   = (const float*)d_in[7];
    const float* bv   = (const float*)d_in[8];
    const float* Wfc  = (const float*)d_in[9];
    const float* bfc  = (const float*)d_in[10];
    const float* Wo   = (const float*)d_in[11];
    const float* bo   = (const float*)d_in[12];
    int V = in_sizes[2] / DD;

    k_q<<<DD, 256>>>(text, emb, Wq, bq, V);
    dim3 gq1(4, QKC);
    k_qk1<<<gq1, 256>>>(Wk);
    k_qk2<<<64, 256>>>();
    dim3 gat(NPART, BB);
    k_attn<<<gat, 256>>>(emb, 1.0f / 32.0f);
    k_attn2<<<BB, 256>>>();
    k_v<<<DD, 256>>>(emb, Wv, bv);
    k_fc<<<DD, 256>>>(Wfc, bfc);
    k_out<<<BB, 256>>>(Wo, bo, (float*)d_out);
}